// round 1
// baseline (speedup 1.0000x reference)
#include <cuda_runtime.h>

#define NWL 112
#define NW  111          // END - START
#define ATM 84           // 21 * 4
#define WARPS_PER_BLOCK 8
#define THREADS (WARPS_PER_BLOCK * 32)

__device__ double g_base_sum;
__device__ double g_wfa_sum;
__device__ unsigned long long g_cnt;

__global__ void wfa_zero_kernel() {
    g_base_sum = 0.0;
    g_wfa_sum  = 0.0;
    g_cnt      = 0ull;
}

__global__ void wfa_main_kernel(const float* __restrict__ stokes,
                                const float* __restrict__ pred,
                                const float* __restrict__ targ,
                                const float* __restrict__ wl,
                                int B) {
    const int tid  = threadIdx.x;
    const int lane = tid & 31;
    const int warp = tid >> 5;
    const int gwarp  = blockIdx.x * WARPS_PER_BLOCK + warp;
    const int nwarps = gridDim.x * WARPS_PER_BLOCK;

    // 1 / (WFA_C * LAMBDA0^2 * G_FACTOR)
    const float inv_cal = 1.0f / (4.6686e-13f * (6301.5f * 6301.5f) * 1.5f);

    double local_wfa = 0.0;
    unsigned int local_cnt = 0;

    // ---------------- WFA regression: one warp per batch row ----------------
    for (int b = gwarp; b < B; b += nwarps) {
        const float* I = stokes + (size_t)b * 4 * NWL;        // Stokes I, wl 0..110
        const float* V = I + 3 * NWL;                          // Stokes V
        float sd = 0.f, sv = 0.f, sdd = 0.f, sdv = 0.f;
        #pragma unroll
        for (int jj = 0; jj < 4; jj++) {
            int j = lane + jj * 32;
            if (j < NW) {
                float di, gw;
                if (j == 0)            { di = I[1] - I[0];           gw = wl[1] - wl[0]; }
                else if (j == NW - 1)  { di = I[NW-1] - I[NW-2];     gw = wl[NW-1] - wl[NW-2]; }
                else                   { di = 0.5f * (I[j+1] - I[j-1]); gw = 0.5f * (wl[j+1] - wl[j-1]); }
                di = di / gw;
                float v = V[j];
                sd  += di;
                sv  += v;
                sdd += di * di;
                sdv += di * v;
            }
        }
        #pragma unroll
        for (int off = 16; off; off >>= 1) {
            sd  += __shfl_down_sync(0xffffffffu, sd,  off);
            sv  += __shfl_down_sync(0xffffffffu, sv,  off);
            sdd += __shfl_down_sync(0xffffffffu, sdd, off);
            sdv += __shfl_down_sync(0xffffffffu, sdv, off);
        }
        if (lane == 0) {
            const float n = (float)NW;
            float p0   = (n * sdv - sd * sv) / (n * sdd - sd * sd);
            float blos = -p0 * inv_cal;
            if (fabsf(blos) < 100.0f) {
                const float* a = pred + (size_t)b * ATM;
                // atm.reshape(21,4)[TAU_IDX={0,1,2}, -1] -> flat idx 3,7,11
                float pb = (a[3] + a[7] + a[11]) * (1.0f / 3.0f);
                float diff = fabsf(log10f(fabsf(pb) + 1e-10f) -
                                   log10f(fabsf(blos) + 1e-10f));
                local_wfa += (double)diff;
                local_cnt += 1u;
            }
        }
    }

    // ---------------- base loss: grid-stride float4 over B*84 ----------------
    float local_base = 0.f;
    {
        const size_t total4 = ((size_t)B * ATM) >> 2;       // B*84 divisible by 4
        const float4* p4 = (const float4*)pred;
        const float4* t4 = (const float4*)targ;
        size_t i      = (size_t)blockIdx.x * blockDim.x + tid;
        size_t stride = (size_t)gridDim.x * blockDim.x;
        for (; i < total4; i += stride) {
            float4 p = p4[i], t = t4[i];
            local_base += fabsf(p.x - t.x) + fabsf(p.y - t.y)
                        + fabsf(p.z - t.z) + fabsf(p.w - t.w);
        }
    }
    #pragma unroll
    for (int off = 16; off; off >>= 1)
        local_base += __shfl_down_sync(0xffffffffu, local_base, off);

    // ---------------- block reduce + one atomic set per block ----------------
    __shared__ double s_wfa[WARPS_PER_BLOCK];
    __shared__ double s_base[WARPS_PER_BLOCK];
    __shared__ unsigned int s_cnt[WARPS_PER_BLOCK];
    if (lane == 0) {
        s_wfa[warp]  = local_wfa;
        s_base[warp] = (double)local_base;
        s_cnt[warp]  = local_cnt;
    }
    __syncthreads();
    if (tid == 0) {
        double w = 0.0, bs = 0.0;
        unsigned long long c = 0;
        #pragma unroll
        for (int i = 0; i < WARPS_PER_BLOCK; i++) {
            w  += s_wfa[i];
            bs += s_base[i];
            c  += s_cnt[i];
        }
        atomicAdd(&g_base_sum, bs);
        if (w != 0.0) atomicAdd(&g_wfa_sum, w);
        if (c)        atomicAdd(&g_cnt, c);
    }
}

__global__ void wfa_final_kernel(float* __restrict__ out, int B) {
    double base = g_base_sum / ((double)B * (double)ATM);
    unsigned long long cnt = g_cnt;
    double wfa_m = g_wfa_sum / (double)(cnt > 0 ? cnt : 1);
    bool apply = (base < 0.0004) && (cnt > 0);
    float total = apply ? (float)(0.5 * base + 0.5 * wfa_m) : (float)base;
    out[0] = total;
    out[1] = (float)base;
    out[2] = apply ? (float)wfa_m : 0.0f;
}

extern "C" void kernel_launch(void* const* d_in, const int* in_sizes, int n_in,
                              void* d_out, int out_size) {
    const float* stokes = (const float*)d_in[0];   // (B, 4, 112)
    const float* pred   = (const float*)d_in[1];   // (B, 84)
    const float* targ   = (const float*)d_in[2];   // (B, 84)
    const float* wl     = (const float*)d_in[3];   // (112,)
    const int B = in_sizes[0] / (4 * NWL);

    float* out = (float*)d_out;

    wfa_zero_kernel<<<1, 1>>>();
    int blocks = (B + WARPS_PER_BLOCK - 1) / WARPS_PER_BLOCK;   // 1 row per warp
    wfa_main_kernel<<<blocks, THREADS>>>(stokes, pred, targ, wl, B);
    wfa_final_kernel<<<1, 1>>>(out, B);
}

// round 3
// speedup vs baseline: 2.0924x; 2.0924x over previous
#include <cuda_runtime.h>

#define NWL 112
#define NW  111
#define ATM 84
#define THREADS 256
#define WPB (THREADS / 32)
#define BLOCKS 1024

__device__ double g_base_sum;            // zero-initialized at load; reset by finalizer
__device__ double g_wfa_sum;
__device__ unsigned long long g_cnt;
__device__ unsigned int g_done;

__global__ void __launch_bounds__(THREADS)
wfa_fused_kernel(const float* __restrict__ stokes,
                 const float* __restrict__ pred,
                 const float* __restrict__ targ,
                 const float* __restrict__ wl,
                 float* __restrict__ out, int B) {
    const int tid   = threadIdx.x;
    const int lane  = tid & 31;
    const int warp  = tid >> 5;
    const int gwarp = blockIdx.x * WPB + warp;
    const int nwarps = gridDim.x * WPB;

    const float inv_cal = 1.0f / (4.6686e-13f * (6301.5f * 6301.5f) * 1.5f);
    const bool act = (lane < 28);               // 28 float4 cover wl/I/V [0..111]

    // ---- per-lane inverse wavelength gradient (row-invariant, computed once) ----
    float4 ig = make_float4(0.f, 0.f, 0.f, 0.f);
    float4 w4 = act ? ((const float4*)wl)[lane] : make_float4(0.f, 0.f, 0.f, 0.f);
    float wprev = __shfl_up_sync(0xffffffffu, w4.w, 1);
    float wnext = __shfl_down_sync(0xffffffffu, w4.x, 1);
    if (act) {
        float g0 = (lane == 0)  ? (w4.y - w4.x) : 0.5f * (w4.y - wprev);
        float g1 = 0.5f * (w4.z - w4.x);
        float g2 = (lane == 27) ? (w4.z - w4.y) : 0.5f * (w4.w - w4.y);
        ig.x = 1.0f / g0;
        ig.y = 1.0f / g1;
        ig.z = 1.0f / g2;
        ig.w = (lane == 27) ? 0.0f : 1.0f / (0.5f * (wnext - w4.z));  // j=111 excluded
    }

    double local_wfa = 0.0;
    unsigned int local_cnt = 0;

    // ---------------- WFA regression: warp per row, float4 lanes ----------------
    for (int b = gwarp; b < B; b += nwarps) {
        const float* row = stokes + (size_t)b * (4 * NWL);
        float4 iv = act ? ((const float4*)row)[lane]             : make_float4(0.f,0.f,0.f,0.f);
        float4 vv = act ? ((const float4*)(row + 3 * NWL))[lane] : make_float4(0.f,0.f,0.f,0.f);
        float iprev = __shfl_up_sync(0xffffffffu, iv.w, 1);
        float inext = __shfl_down_sync(0xffffffffu, iv.x, 1);

        float sd = 0.f, sv = 0.f, sdd = 0.f, sdv = 0.f;
        if (act) {
            float d0 = ((lane == 0)  ? (iv.y - iv.x) : 0.5f * (iv.y - iprev)) * ig.x;
            float d1 = 0.5f * (iv.z - iv.x) * ig.y;
            float d2 = ((lane == 27) ? (iv.z - iv.y) : 0.5f * (iv.w - iv.y)) * ig.z;
            float d3 = 0.5f * (inext - iv.z) * ig.w;       // ig.w==0 on lane 27 -> 0
            float v3 = (lane == 27) ? 0.0f : vv.w;          // j=111 excluded
            sd  = d0 + d1 + d2 + d3;
            sv  = vv.x + vv.y + vv.z + v3;
            sdd = d0 * d0 + d1 * d1 + d2 * d2 + d3 * d3;
            sdv = d0 * vv.x + d1 * vv.y + d2 * vv.z + d3 * v3;
        }
        #pragma unroll
        for (int off = 16; off; off >>= 1) {
            sd  += __shfl_xor_sync(0xffffffffu, sd,  off);
            sv  += __shfl_xor_sync(0xffffffffu, sv,  off);
            sdd += __shfl_xor_sync(0xffffffffu, sdd, off);
            sdv += __shfl_xor_sync(0xffffffffu, sdv, off);
        }
        if (lane == 0) {
            const float n = (float)NW;
            float p0   = (n * sdv - sd * sv) / (n * sdd - sd * sd);
            float blos = -p0 * inv_cal;
            if (fabsf(blos) < 100.0f) {
                const float* a = pred + (size_t)b * ATM;
                float pb = (a[3] + a[7] + a[11]) * (1.0f / 3.0f);
                local_wfa += (double)fabsf(log10f(fabsf(pb)  + 1e-10f) -
                                           log10f(fabsf(blos) + 1e-10f));
                local_cnt += 1u;
            }
        }
    }

    // ---------------- base loss: grid-stride float4 over B*84 ----------------
    float local_base = 0.f;
    {
        const size_t total4 = ((size_t)B * ATM) >> 2;
        const float4* p4 = (const float4*)pred;
        const float4* t4 = (const float4*)targ;
        size_t i      = (size_t)blockIdx.x * THREADS + tid;
        size_t stride = (size_t)gridDim.x * THREADS;
        for (; i < total4; i += stride) {
            float4 p = p4[i], t = t4[i];
            local_base += fabsf(p.x - t.x) + fabsf(p.y - t.y)
                        + fabsf(p.z - t.z) + fabsf(p.w - t.w);
        }
    }

    // ---------------- block reduction ----------------
    #pragma unroll
    for (int off = 16; off; off >>= 1) {
        local_base += __shfl_xor_sync(0xffffffffu, local_base, off);
        local_wfa  += __shfl_xor_sync(0xffffffffu, local_wfa,  off);
        local_cnt  += __shfl_xor_sync(0xffffffffu, local_cnt,  off);
    }
    __shared__ double s_wfa[WPB];
    __shared__ float  s_base[WPB];
    __shared__ unsigned int s_cnt[WPB];
    if (lane == 0) { s_wfa[warp] = local_wfa; s_base[warp] = local_base; s_cnt[warp] = local_cnt; }
    __syncthreads();

    __shared__ bool s_last;
    if (tid == 0) {
        double w = 0.0; double bs = 0.0; unsigned long long c = 0;
        #pragma unroll
        for (int i = 0; i < WPB; i++) { w += s_wfa[i]; bs += (double)s_base[i]; c += s_cnt[i]; }
        atomicAdd(&g_base_sum, bs);
        if (w != 0.0) atomicAdd(&g_wfa_sum, w);
        if (c)        atomicAdd(&g_cnt, c);
        __threadfence();
        unsigned int prev = atomicAdd(&g_done, 1u);
        s_last = (prev == gridDim.x - 1);
    }
    __syncthreads();

    // ---------------- last block finalizes and resets state ----------------
    if (s_last && tid == 0) {
        double base = *((volatile double*)&g_base_sum) / ((double)B * (double)ATM);
        unsigned long long cnt = *((volatile unsigned long long*)&g_cnt);
        double wfa_m = *((volatile double*)&g_wfa_sum) / (double)(cnt > 0 ? cnt : 1);
        bool apply = (base < 0.0004) && (cnt > 0);
        out[0] = apply ? (float)(0.5 * base + 0.5 * wfa_m) : (float)base;
        out[1] = (float)base;
        out[2] = apply ? (float)wfa_m : 0.0f;
        // reset for next graph replay
        g_base_sum = 0.0;
        g_wfa_sum  = 0.0;
        g_cnt      = 0ull;
        g_done     = 0u;
        __threadfence();
    }
}

extern "C" void kernel_launch(void* const* d_in, const int* in_sizes, int n_in,
                              void* d_out, int out_size) {
    const float* stokes = (const float*)d_in[0];   // (B, 4, 112)
    const float* pred   = (const float*)d_in[1];   // (B, 84)
    const float* targ   = (const float*)d_in[2];   // (B, 84)
    const float* wl     = (const float*)d_in[3];   // (112,)
    const int B = in_sizes[0] / (4 * NWL);
    wfa_fused_kernel<<<BLOCKS, THREADS>>>(stokes, pred, targ, wl, (float*)d_out, B);
}

// round 5
// speedup vs baseline: 2.2781x; 1.0888x over previous
#include <cuda_runtime.h>

#define NWL 112
#define NW  111
#define ATM 84
#define THREADS 256
#define WPB (THREADS / 32)
#define BLOCKS 740            // 148 SMs * 5 resident blocks -> single wave

__device__ double g_base_sum;   // zero-init at load; reset by finalizer each run
__device__ double g_wfa_sum;
__device__ unsigned long long g_cnt;
__device__ unsigned int g_done;

__global__ void __launch_bounds__(THREADS, 5)
wfa_fused_kernel(const float* __restrict__ stokes,
                 const float* __restrict__ pred,
                 const float* __restrict__ targ,
                 const float* __restrict__ wl,
                 float* __restrict__ out, int B) {
    const int tid   = threadIdx.x;
    const int lane  = tid & 31;
    const int warp  = tid >> 5;
    const int gwarp = blockIdx.x * WPB + warp;
    const int nwarps = gridDim.x * WPB;
    const unsigned FULL = 0xffffffffu;

    const float inv_cal = 1.0f / (4.6686e-13f * (6301.5f * 6301.5f) * 1.5f);
    const bool act = (lane < 28);                // 28 float4 cover [0..111]

    // ---- per-lane inverse wavelength gradient (row-invariant) ----
    float4 ig = make_float4(0.f, 0.f, 0.f, 0.f);
    float4 w4 = act ? ((const float4*)wl)[lane] : make_float4(0.f, 0.f, 0.f, 0.f);
    float wprev = __shfl_up_sync(FULL, w4.w, 1);
    float wnext = __shfl_down_sync(FULL, w4.x, 1);
    if (act) {
        float g0 = (lane == 0)  ? (w4.y - w4.x) : 0.5f * (w4.y - wprev);
        float g1 = 0.5f * (w4.z - w4.x);
        float g2 = (lane == 27) ? (w4.z - w4.y) : 0.5f * (w4.w - w4.y);
        ig.x = 1.0f / g0;
        ig.y = 1.0f / g1;
        ig.z = 1.0f / g2;
        ig.w = (lane == 27) ? 0.0f : 1.0f / (0.5f * (wnext - w4.z));  // j=111 excluded
    }

    double local_wfa = 0.0;
    unsigned int local_cnt = 0;

    // ------------- WFA regression: warp per row, prefetch-pipelined -------------
    int b = gwarp;
    float4 iv = make_float4(0.f,0.f,0.f,0.f), vv = make_float4(0.f,0.f,0.f,0.f);
    if (b < B && act) {
        const float* row = stokes + (size_t)b * (4 * NWL);
        iv = ((const float4*)row)[lane];
        vv = ((const float4*)(row + 3 * NWL))[lane];
    }
    while (b < B) {
        const int bn = b + nwarps;
        float4 ivn = make_float4(0.f,0.f,0.f,0.f), vvn = make_float4(0.f,0.f,0.f,0.f);
        if (bn < B && act) {                       // prefetch next row
            const float* rown = stokes + (size_t)bn * (4 * NWL);
            ivn = ((const float4*)rown)[lane];
            vvn = ((const float4*)(rown + 3 * NWL))[lane];
        }

        float iprev = __shfl_up_sync(FULL, iv.w, 1);
        float inext = __shfl_down_sync(FULL, iv.x, 1);
        float sd = 0.f, sv = 0.f, sdd = 0.f, sdv = 0.f;
        if (act) {
            float d0 = ((lane == 0)  ? (iv.y - iv.x) : 0.5f * (iv.y - iprev)) * ig.x;
            float d1 = 0.5f * (iv.z - iv.x) * ig.y;
            float d2 = ((lane == 27) ? (iv.z - iv.y) : 0.5f * (iv.w - iv.y)) * ig.z;
            float d3 = 0.5f * (inext - iv.z) * ig.w;   // ig.w==0 on lane 27
            float v3 = (lane == 27) ? 0.0f : vv.w;      // j=111 excluded
            sd  = d0 + d1 + d2 + d3;
            sv  = vv.x + vv.y + vv.z + v3;
            sdd = d0 * d0 + d1 * d1 + d2 * d2 + d3 * d3;
            sdv = d0 * vv.x + d1 * vv.y + d2 * vv.z + d3 * v3;
        }

        // ---- packed 4-value butterfly: 9 SHFL + 4 broadcasts ----
        float a = sd  + __shfl_xor_sync(FULL, sd,  1);
        float bb= sv  + __shfl_xor_sync(FULL, sv,  1);
        float c = sdd + __shfl_xor_sync(FULL, sdd, 1);
        float d = sdv + __shfl_xor_sync(FULL, sdv, 1);
        float p = (lane & 1) ? bb : a;   // even lanes: sd-partial, odd: sv-partial
        float q = (lane & 1) ? d  : c;
        p += __shfl_xor_sync(FULL, p, 2);
        q += __shfl_xor_sync(FULL, q, 2);
        float r = (lane & 2) ? q : p;    // lane%4 = 0:sd 1:sv 2:sdd 3:sdv
        r += __shfl_xor_sync(FULL, r, 4);
        r += __shfl_xor_sync(FULL, r, 8);
        r += __shfl_xor_sync(FULL, r, 16);
        float sd_t  = __shfl_sync(FULL, r, 0);
        float sv_t  = __shfl_sync(FULL, r, 1);
        float sdd_t = __shfl_sync(FULL, r, 2);
        float sdv_t = __shfl_sync(FULL, r, 3);

        if (lane == 0) {
            const float n = (float)NW;
            float p0   = (n * sdv_t - sd_t * sv_t) / (n * sdd_t - sd_t * sd_t);
            float blos = -p0 * inv_cal;
            if (fabsf(blos) < 100.0f) {
                const float* aptr = pred + (size_t)b * ATM;
                float pb = (aptr[3] + aptr[7] + aptr[11]) * (1.0f / 3.0f);
                local_wfa += (double)fabsf(log10f(fabsf(pb)  + 1e-10f) -
                                           log10f(fabsf(blos) + 1e-10f));
                local_cnt += 1u;
            }
        }
        iv = ivn; vv = vvn; b = bn;
    }

    // ------------- base loss: grid-stride float4 over B*84 -------------
    float local_base = 0.f;
    {
        const size_t total4 = ((size_t)B * ATM) >> 2;
        const float4* p4 = (const float4*)pred;
        const float4* t4 = (const float4*)targ;
        size_t i      = (size_t)blockIdx.x * THREADS + tid;
        size_t stride = (size_t)gridDim.x * THREADS;
        #pragma unroll 2
        for (; i < total4; i += stride) {
            float4 p = p4[i], t = t4[i];
            local_base += fabsf(p.x - t.x) + fabsf(p.y - t.y)
                        + fabsf(p.z - t.z) + fabsf(p.w - t.w);
        }
    }

    // ------------- warp + block reduction -------------
    #pragma unroll
    for (int off = 16; off; off >>= 1) {
        local_base += __shfl_xor_sync(FULL, local_base, off);
        local_wfa  += __shfl_xor_sync(FULL, local_wfa,  off);
        local_cnt  += __shfl_xor_sync(FULL, local_cnt,  off);
    }
    __shared__ double s_wfa[WPB];
    __shared__ float  s_base[WPB];
    __shared__ unsigned int s_cnt[WPB];
    if (lane == 0) { s_wfa[warp] = local_wfa; s_base[warp] = local_base; s_cnt[warp] = local_cnt; }
    __syncthreads();

    __shared__ bool s_last;
    if (tid == 0) {
        double w = 0.0, bs = 0.0; unsigned long long c = 0;
        #pragma unroll
        for (int i = 0; i < WPB; i++) { w += s_wfa[i]; bs += (double)s_base[i]; c += s_cnt[i]; }
        atomicAdd(&g_base_sum, bs);
        if (w != 0.0) atomicAdd(&g_wfa_sum, w);
        if (c)        atomicAdd(&g_cnt, c);
        __threadfence();
        unsigned int prev = atomicAdd(&g_done, 1u);
        s_last = (prev == gridDim.x - 1);
    }
    __syncthreads();

    // ------------- last block finalizes + resets for next replay -------------
    if (s_last && tid == 0) {
        double base = *((volatile double*)&g_base_sum) / ((double)B * (double)ATM);
        unsigned long long cnt = *((volatile unsigned long long*)&g_cnt);
        double wfa_m = *((volatile double*)&g_wfa_sum) / (double)(cnt > 0 ? cnt : 1);
        bool apply = (base < 0.0004) && (cnt > 0);
        out[0] = apply ? (float)(0.5 * base + 0.5 * wfa_m) : (float)base;
        out[1] = (float)base;
        out[2] = apply ? (float)wfa_m : 0.0f;
        g_base_sum = 0.0;
        g_wfa_sum  = 0.0;
        g_cnt      = 0ull;
        g_done     = 0u;
        __threadfence();
    }
}

extern "C" void kernel_launch(void* const* d_in, const int* in_sizes, int n_in,
                              void* d_out, int out_size) {
    const float* stokes = (const float*)d_in[0];   // (B, 4, 112)
    const float* pred   = (const float*)d_in[1];   // (B, 84)
    const float* targ   = (const float*)d_in[2];   // (B, 84)
    const float* wl     = (const float*)d_in[3];   // (112,)
    const int B = in_sizes[0] / (4 * NWL);
    wfa_fused_kernel<<<BLOCKS, THREADS>>>(stokes, pred, targ, wl, (float*)d_out, B);
}

// round 7
// speedup vs baseline: 2.7241x; 1.1958x over previous
#include <cuda_runtime.h>

#define NWL 112
#define NW  111
#define ATM 84
#define THREADS 256
#define WPB (THREADS / 32)
#define BLOCKS 740            // 148 SMs * 5 resident blocks -> single wave

__device__ double g_base_sum;   // zero-init at load; reset by finalizer each run
__device__ double g_wfa_sum;
__device__ unsigned long long g_cnt;
__device__ unsigned int g_done;

__global__ void __launch_bounds__(THREADS, 5)
wfa_fused_kernel(const float* __restrict__ stokes,
                 const float* __restrict__ pred,
                 const float* __restrict__ targ,
                 const float* __restrict__ wl,
                 float* __restrict__ out, int B) {
    const int tid   = threadIdx.x;
    const int lane  = tid & 31;
    const int warp  = tid >> 5;
    const int gwarp = blockIdx.x * WPB + warp;
    const int nwarps = gridDim.x * WPB;
    const unsigned FULL = 0xffffffffu;

    const float inv_cal = 1.0f / (4.6686e-13f * (6301.5f * 6301.5f) * 1.5f);
    const bool act = (lane < 28);                // 28 float4 cover [0..111]

    // ---- per-lane inverse wavelength gradient (row-invariant) ----
    float4 ig = make_float4(0.f, 0.f, 0.f, 0.f);
    float4 w4 = act ? ((const float4*)wl)[lane] : make_float4(0.f, 0.f, 0.f, 0.f);
    float wprev = __shfl_up_sync(FULL, w4.w, 1);
    float wnext = __shfl_down_sync(FULL, w4.x, 1);
    if (act) {
        float g0 = (lane == 0)  ? (w4.y - w4.x) : 0.5f * (w4.y - wprev);
        float g1 = 0.5f * (w4.z - w4.x);
        float g2 = (lane == 27) ? (w4.z - w4.y) : 0.5f * (w4.w - w4.y);
        ig.x = 1.0f / g0;
        ig.y = 1.0f / g1;
        ig.z = 1.0f / g2;
        ig.w = (lane == 27) ? 0.0f : 1.0f / (0.5f * (wnext - w4.z));  // j=111 excluded
    }

    double local_wfa = 0.0;
    unsigned int local_cnt = 0;

    // ---- WFA regression: warp handles row pair (b, b+1); B even so pairs always whole ----
    const int pstep = 2 * nwarps;
    int b = 2 * gwarp;
    float4 iv0, vv0, iv1, vv1;
    if (b < B && act) {
        const float* r0 = stokes + (size_t)b * (4 * NWL);
        iv0 = ((const float4*)r0)[lane];
        vv0 = ((const float4*)(r0 + 3 * NWL))[lane];
        iv1 = ((const float4*)(r0 + 4 * NWL))[lane];
        vv1 = ((const float4*)(r0 + 7 * NWL))[lane];
    } else {
        iv0 = iv1 = vv0 = vv1 = make_float4(0.f,0.f,0.f,0.f);
    }

    while (b < B) {
        const int bn = b + pstep;
        float4 ivn0, vvn0, ivn1, vvn1;
        if (bn < B && act) {                       // prefetch next pair
            const float* rn = stokes + (size_t)bn * (4 * NWL);
            ivn0 = ((const float4*)rn)[lane];
            vvn0 = ((const float4*)(rn + 3 * NWL))[lane];
            ivn1 = ((const float4*)(rn + 4 * NWL))[lane];
            vvn1 = ((const float4*)(rn + 7 * NWL))[lane];
        } else {
            ivn0 = ivn1 = vvn0 = vvn1 = make_float4(0.f,0.f,0.f,0.f);
        }

        float ip0 = __shfl_up_sync(FULL, iv0.w, 1);
        float in0 = __shfl_down_sync(FULL, iv0.x, 1);
        float ip1 = __shfl_up_sync(FULL, iv1.w, 1);
        float in1 = __shfl_down_sync(FULL, iv1.x, 1);

        float v0=0.f,v1=0.f,v2=0.f,v3=0.f,v4=0.f,v5=0.f,v6=0.f,v7=0.f;
        if (act) {
            // row 0
            float d0 = ((lane == 0)  ? (iv0.y - iv0.x) : 0.5f * (iv0.y - ip0)) * ig.x;
            float d1 = 0.5f * (iv0.z - iv0.x) * ig.y;
            float d2 = ((lane == 27) ? (iv0.z - iv0.y) : 0.5f * (iv0.w - iv0.y)) * ig.z;
            float d3 = 0.5f * (in0 - iv0.z) * ig.w;
            float vw0 = (lane == 27) ? 0.0f : vv0.w;
            v0 = d0 + d1 + d2 + d3;
            v1 = vv0.x + vv0.y + vv0.z + vw0;
            v2 = d0*d0 + d1*d1 + d2*d2 + d3*d3;
            v3 = d0*vv0.x + d1*vv0.y + d2*vv0.z + d3*vw0;
            // row 1
            float e0 = ((lane == 0)  ? (iv1.y - iv1.x) : 0.5f * (iv1.y - ip1)) * ig.x;
            float e1 = 0.5f * (iv1.z - iv1.x) * ig.y;
            float e2 = ((lane == 27) ? (iv1.z - iv1.y) : 0.5f * (iv1.w - iv1.y)) * ig.z;
            float e3 = 0.5f * (in1 - iv1.z) * ig.w;
            float vw1 = (lane == 27) ? 0.0f : vv1.w;
            v4 = e0 + e1 + e2 + e3;
            v5 = vv1.x + vv1.y + vv1.z + vw1;
            v6 = e0*e0 + e1*e1 + e2*e2 + e3*e3;
            v7 = e0*vv1.x + e1*vv1.y + e2*vv1.z + e3*vw1;
        }

        // ---- joint 8-value packed butterfly: 16 SHFL ----
        v0 += __shfl_xor_sync(FULL, v0, 1);
        v1 += __shfl_xor_sync(FULL, v1, 1);
        v2 += __shfl_xor_sync(FULL, v2, 1);
        v3 += __shfl_xor_sync(FULL, v3, 1);
        v4 += __shfl_xor_sync(FULL, v4, 1);
        v5 += __shfl_xor_sync(FULL, v5, 1);
        v6 += __shfl_xor_sync(FULL, v6, 1);
        v7 += __shfl_xor_sync(FULL, v7, 1);
        float p0 = (lane & 1) ? v1 : v0;
        float p1 = (lane & 1) ? v3 : v2;
        float p2 = (lane & 1) ? v5 : v4;
        float p3 = (lane & 1) ? v7 : v6;
        p0 += __shfl_xor_sync(FULL, p0, 2);
        p1 += __shfl_xor_sync(FULL, p1, 2);
        p2 += __shfl_xor_sync(FULL, p2, 2);
        p3 += __shfl_xor_sync(FULL, p3, 2);
        float q0 = (lane & 2) ? p1 : p0;
        float q1 = (lane & 2) ? p3 : p2;
        q0 += __shfl_xor_sync(FULL, q0, 4);
        q1 += __shfl_xor_sync(FULL, q1, 4);
        float r = (lane & 4) ? q1 : q0;
        r += __shfl_xor_sync(FULL, r, 8);
        r += __shfl_xor_sync(FULL, r, 16);
        // lane l holds total of value index (l&7): 0:sd0 1:sv0 2:sdd0 3:sdv0 4:sd1 ...

        // gather per-row sums to lanes 0 (row b) and 4 (row b+1)
        const int base = lane & 4;
        float sd_t  = __shfl_sync(FULL, r, base + 0);
        float sv_t  = __shfl_sync(FULL, r, base + 1);
        float sdd_t = __shfl_sync(FULL, r, base + 2);
        float sdv_t = __shfl_sync(FULL, r, base + 3);

        if ((lane & 27) == 0) {       // lanes 0 and 4, same path
            const int myb = b + (lane >> 2);
            const float n = (float)NW;
            float pp   = (n * sdv_t - sd_t * sv_t) / (n * sdd_t - sd_t * sd_t);
            float blos = -pp * inv_cal;
            if (fabsf(blos) < 100.0f) {
                const float* aptr = pred + (size_t)myb * ATM;
                float pb = (aptr[3] + aptr[7] + aptr[11]) * (1.0f / 3.0f);
                local_wfa += (double)fabsf(log10f(fabsf(pb)  + 1e-10f) -
                                           log10f(fabsf(blos) + 1e-10f));
                local_cnt += 1u;
            }
        }
        iv0 = ivn0; vv0 = vvn0; iv1 = ivn1; vv1 = vvn1; b = bn;
    }

    // ------------- base loss: grid-stride float4 over B*84 -------------
    float local_base = 0.f;
    {
        const size_t total4 = ((size_t)B * ATM) >> 2;
        const float4* p4 = (const float4*)pred;
        const float4* t4 = (const float4*)targ;
        size_t i      = (size_t)blockIdx.x * THREADS + tid;
        size_t stride = (size_t)gridDim.x * THREADS;
        #pragma unroll 2
        for (; i < total4; i += stride) {
            float4 p = p4[i], t = t4[i];
            local_base += fabsf(p.x - t.x) + fabsf(p.y - t.y)
                        + fabsf(p.z - t.z) + fabsf(p.w - t.w);
        }
    }

    // ------------- warp + block reduction -------------
    #pragma unroll
    for (int off = 16; off; off >>= 1) {
        local_base += __shfl_xor_sync(FULL, local_base, off);
        local_wfa  += __shfl_xor_sync(FULL, local_wfa,  off);
        local_cnt  += __shfl_xor_sync(FULL, local_cnt,  off);
    }
    __shared__ double s_wfa[WPB];
    __shared__ float  s_base[WPB];
    __shared__ unsigned int s_cnt[WPB];
    if (lane == 0) { s_wfa[warp] = local_wfa; s_base[warp] = local_base; s_cnt[warp] = local_cnt; }
    __syncthreads();

    __shared__ bool s_last;
    if (tid == 0) {
        double w = 0.0, bs = 0.0; unsigned long long c = 0;
        #pragma unroll
        for (int i = 0; i < WPB; i++) { w += s_wfa[i]; bs += (double)s_base[i]; c += s_cnt[i]; }
        atomicAdd(&g_base_sum, bs);
        if (w != 0.0) atomicAdd(&g_wfa_sum, w);
        if (c)        atomicAdd(&g_cnt, c);
        __threadfence();
        unsigned int prev = atomicAdd(&g_done, 1u);
        s_last = (prev == gridDim.x - 1);
    }
    __syncthreads();

    // ------------- last block finalizes + resets for next replay -------------
    if (s_last && tid == 0) {
        double base = *((volatile double*)&g_base_sum) / ((double)B * (double)ATM);
        unsigned long long cnt = *((volatile unsigned long long*)&g_cnt);
        double wfa_m = *((volatile double*)&g_wfa_sum) / (double)(cnt > 0 ? cnt : 1);
        bool apply = (base < 0.0004) && (cnt > 0);
        out[0] = apply ? (float)(0.5 * base + 0.5 * wfa_m) : (float)base;
        out[1] = (float)base;
        out[2] = apply ? (float)wfa_m : 0.0f;
        g_base_sum = 0.0;
        g_wfa_sum  = 0.0;
        g_cnt      = 0ull;
        g_done     = 0u;
        __threadfence();
    }
}

extern "C" void kernel_launch(void* const* d_in, const int* in_sizes, int n_in,
                              void* d_out, int out_size) {
    const float* stokes = (const float*)d_in[0];   // (B, 4, 112)
    const float* pred   = (const float*)d_in[1];   // (B, 84)
    const float* targ   = (const float*)d_in[2];   // (B, 84)
    const float* wl     = (const float*)d_in[3];   // (112,)
    const int B = in_sizes[0] / (4 * NWL);
    wfa_fused_kernel<<<BLOCKS, THREADS>>>(stokes, pred, targ, wl, (float*)d_out, B);
}

// round 8
// speedup vs baseline: 2.7698x; 1.0168x over previous
#include <cuda_runtime.h>

#define NWL 112
#define NW  111
#define ATM 84
#define THREADS 256
#define WPB (THREADS / 32)
#define WFA_WARPS 6
#define BASE_WARPS (WPB - WFA_WARPS)
#define BLOCKS 740            // 148 SMs * 5 resident blocks -> single wave

__device__ double g_base_sum;   // zero-init at load; reset by finalizer each run
__device__ double g_wfa_sum;
__device__ unsigned long long g_cnt;
__device__ unsigned int g_done;

__global__ void __launch_bounds__(THREADS, 5)
wfa_fused_kernel(const float* __restrict__ stokes,
                 const float* __restrict__ pred,
                 const float* __restrict__ targ,
                 const float* __restrict__ wl,
                 float* __restrict__ out, int B) {
    const int tid   = threadIdx.x;
    const int lane  = tid & 31;
    const int warp  = tid >> 5;
    const unsigned FULL = 0xffffffffu;

    double local_wfa = 0.0;
    float  local_base = 0.f;
    unsigned int local_cnt = 0;

    if (warp < WFA_WARPS) {
        // ================= WFA warps: warp per row-pair, pipelined =================
        const int gwarp  = blockIdx.x * WFA_WARPS + warp;
        const int nwarps = BLOCKS * WFA_WARPS;
        const float inv_cal = 1.0f / (4.6686e-13f * (6301.5f * 6301.5f) * 1.5f);
        const bool act = (lane < 28);            // 28 float4 cover [0..111]

        // per-lane inverse wavelength gradient (row-invariant)
        float4 ig = make_float4(0.f, 0.f, 0.f, 0.f);
        float4 w4 = act ? ((const float4*)wl)[lane] : make_float4(0.f, 0.f, 0.f, 0.f);
        float wprev = __shfl_up_sync(FULL, w4.w, 1);
        float wnext = __shfl_down_sync(FULL, w4.x, 1);
        if (act) {
            float g0 = (lane == 0)  ? (w4.y - w4.x) : 0.5f * (w4.y - wprev);
            float g1 = 0.5f * (w4.z - w4.x);
            float g2 = (lane == 27) ? (w4.z - w4.y) : 0.5f * (w4.w - w4.y);
            ig.x = 1.0f / g0;
            ig.y = 1.0f / g1;
            ig.z = 1.0f / g2;
            ig.w = (lane == 27) ? 0.0f : 1.0f / (0.5f * (wnext - w4.z));  // j=111 excluded
        }

        const int pstep = 2 * nwarps;
        int b = 2 * gwarp;
        float4 iv0, vv0, iv1, vv1;
        if (b < B && act) {
            const float* r0 = stokes + (size_t)b * (4 * NWL);
            iv0 = ((const float4*)r0)[lane];
            vv0 = ((const float4*)(r0 + 3 * NWL))[lane];
            iv1 = ((const float4*)(r0 + 4 * NWL))[lane];
            vv1 = ((const float4*)(r0 + 7 * NWL))[lane];
        } else {
            iv0 = iv1 = vv0 = vv1 = make_float4(0.f,0.f,0.f,0.f);
        }

        while (b < B) {
            const int bn = b + pstep;
            float4 ivn0, vvn0, ivn1, vvn1;
            if (bn < B && act) {                  // prefetch next pair
                const float* rn = stokes + (size_t)bn * (4 * NWL);
                ivn0 = ((const float4*)rn)[lane];
                vvn0 = ((const float4*)(rn + 3 * NWL))[lane];
                ivn1 = ((const float4*)(rn + 4 * NWL))[lane];
                vvn1 = ((const float4*)(rn + 7 * NWL))[lane];
            } else {
                ivn0 = ivn1 = vvn0 = vvn1 = make_float4(0.f,0.f,0.f,0.f);
            }

            float ip0 = __shfl_up_sync(FULL, iv0.w, 1);
            float in0 = __shfl_down_sync(FULL, iv0.x, 1);
            float ip1 = __shfl_up_sync(FULL, iv1.w, 1);
            float in1 = __shfl_down_sync(FULL, iv1.x, 1);

            float v0=0.f,v1=0.f,v2=0.f,v3=0.f,v4=0.f,v5=0.f,v6=0.f,v7=0.f;
            if (act) {
                float d0 = ((lane == 0)  ? (iv0.y - iv0.x) : 0.5f * (iv0.y - ip0)) * ig.x;
                float d1 = 0.5f * (iv0.z - iv0.x) * ig.y;
                float d2 = ((lane == 27) ? (iv0.z - iv0.y) : 0.5f * (iv0.w - iv0.y)) * ig.z;
                float d3 = 0.5f * (in0 - iv0.z) * ig.w;
                float vw0 = (lane == 27) ? 0.0f : vv0.w;
                v0 = d0 + d1 + d2 + d3;
                v1 = vv0.x + vv0.y + vv0.z + vw0;
                v2 = d0*d0 + d1*d1 + d2*d2 + d3*d3;
                v3 = d0*vv0.x + d1*vv0.y + d2*vv0.z + d3*vw0;
                float e0 = ((lane == 0)  ? (iv1.y - iv1.x) : 0.5f * (iv1.y - ip1)) * ig.x;
                float e1 = 0.5f * (iv1.z - iv1.x) * ig.y;
                float e2 = ((lane == 27) ? (iv1.z - iv1.y) : 0.5f * (iv1.w - iv1.y)) * ig.z;
                float e3 = 0.5f * (in1 - iv1.z) * ig.w;
                float vw1 = (lane == 27) ? 0.0f : vv1.w;
                v4 = e0 + e1 + e2 + e3;
                v5 = vv1.x + vv1.y + vv1.z + vw1;
                v6 = e0*e0 + e1*e1 + e2*e2 + e3*e3;
                v7 = e0*vv1.x + e1*vv1.y + e2*vv1.z + e3*vw1;
            }

            // joint 8-value packed butterfly: 16 SHFL
            v0 += __shfl_xor_sync(FULL, v0, 1);
            v1 += __shfl_xor_sync(FULL, v1, 1);
            v2 += __shfl_xor_sync(FULL, v2, 1);
            v3 += __shfl_xor_sync(FULL, v3, 1);
            v4 += __shfl_xor_sync(FULL, v4, 1);
            v5 += __shfl_xor_sync(FULL, v5, 1);
            v6 += __shfl_xor_sync(FULL, v6, 1);
            v7 += __shfl_xor_sync(FULL, v7, 1);
            float p0 = (lane & 1) ? v1 : v0;
            float p1 = (lane & 1) ? v3 : v2;
            float p2 = (lane & 1) ? v5 : v4;
            float p3 = (lane & 1) ? v7 : v6;
            p0 += __shfl_xor_sync(FULL, p0, 2);
            p1 += __shfl_xor_sync(FULL, p1, 2);
            p2 += __shfl_xor_sync(FULL, p2, 2);
            p3 += __shfl_xor_sync(FULL, p3, 2);
            float q0 = (lane & 2) ? p1 : p0;
            float q1 = (lane & 2) ? p3 : p2;
            q0 += __shfl_xor_sync(FULL, q0, 4);
            q1 += __shfl_xor_sync(FULL, q1, 4);
            float r = (lane & 4) ? q1 : q0;
            r += __shfl_xor_sync(FULL, r, 8);
            r += __shfl_xor_sync(FULL, r, 16);
            // lane l holds total of value index (l&7)

            const int base = lane & 4;
            float sd_t  = __shfl_sync(FULL, r, base + 0);
            float sv_t  = __shfl_sync(FULL, r, base + 1);
            float sdd_t = __shfl_sync(FULL, r, base + 2);
            float sdv_t = __shfl_sync(FULL, r, base + 3);

            if ((lane & 27) == 0) {       // lanes 0 and 4 run epilogues concurrently
                const int myb = b + (lane >> 2);
                const float n = (float)NW;
                float pp   = (n * sdv_t - sd_t * sv_t) / (n * sdd_t - sd_t * sd_t);
                float blos = -pp * inv_cal;
                if (fabsf(blos) < 100.0f) {
                    const float* aptr = pred + (size_t)myb * ATM;
                    float pb = (aptr[3] + aptr[7] + aptr[11]) * (1.0f / 3.0f);
                    local_wfa += (double)fabsf(log10f(fabsf(pb)  + 1e-10f) -
                                               log10f(fabsf(blos) + 1e-10f));
                    local_cnt += 1u;
                }
            }
            iv0 = ivn0; vv0 = vvn0; iv1 = ivn1; vv1 = vvn1; b = bn;
        }
    } else {
        // ================= base warps: mean |pred - targ| =================
        const int bwarp   = blockIdx.x * BASE_WARPS + (warp - WFA_WARPS);
        const size_t total4 = ((size_t)B * ATM) >> 2;
        const float4* p4 = (const float4*)pred;
        const float4* t4 = (const float4*)targ;
        const size_t stride = (size_t)BLOCKS * BASE_WARPS * 32;
        size_t i = (size_t)bwarp * 32 + lane;

        float a0 = 0.f, a1 = 0.f, a2 = 0.f, a3 = 0.f;
        // 4-deep unroll: 8 independent float4 loads in flight
        for (; i + 3 * stride < total4; i += 4 * stride) {
            float4 pA = p4[i];              float4 tA = t4[i];
            float4 pB = p4[i + stride];     float4 tB = t4[i + stride];
            float4 pC = p4[i + 2 * stride]; float4 tC = t4[i + 2 * stride];
            float4 pD = p4[i + 3 * stride]; float4 tD = t4[i + 3 * stride];
            a0 += fabsf(pA.x - tA.x) + fabsf(pA.y - tA.y) + fabsf(pA.z - tA.z) + fabsf(pA.w - tA.w);
            a1 += fabsf(pB.x - tB.x) + fabsf(pB.y - tB.y) + fabsf(pB.z - tB.z) + fabsf(pB.w - tB.w);
            a2 += fabsf(pC.x - tC.x) + fabsf(pC.y - tC.y) + fabsf(pC.z - tC.z) + fabsf(pC.w - tC.w);
            a3 += fabsf(pD.x - tD.x) + fabsf(pD.y - tD.y) + fabsf(pD.z - tD.z) + fabsf(pD.w - tD.w);
        }
        for (; i < total4; i += stride) {
            float4 p = p4[i], t = t4[i];
            a0 += fabsf(p.x - t.x) + fabsf(p.y - t.y) + fabsf(p.z - t.z) + fabsf(p.w - t.w);
        }
        local_base = (a0 + a1) + (a2 + a3);
    }

    // ------------- warp + block reduction -------------
    #pragma unroll
    for (int off = 16; off; off >>= 1) {
        local_base += __shfl_xor_sync(FULL, local_base, off);
        local_wfa  += __shfl_xor_sync(FULL, local_wfa,  off);
        local_cnt  += __shfl_xor_sync(FULL, local_cnt,  off);
    }
    __shared__ double s_wfa[WPB];
    __shared__ float  s_base[WPB];
    __shared__ unsigned int s_cnt[WPB];
    if (lane == 0) { s_wfa[warp] = local_wfa; s_base[warp] = local_base; s_cnt[warp] = local_cnt; }
    __syncthreads();

    __shared__ bool s_last;
    if (tid == 0) {
        double w = 0.0, bs = 0.0; unsigned long long c = 0;
        #pragma unroll
        for (int i = 0; i < WPB; i++) { w += s_wfa[i]; bs += (double)s_base[i]; c += s_cnt[i]; }
        atomicAdd(&g_base_sum, bs);
        if (w != 0.0) atomicAdd(&g_wfa_sum, w);
        if (c)        atomicAdd(&g_cnt, c);
        __threadfence();
        unsigned int prev = atomicAdd(&g_done, 1u);
        s_last = (prev == gridDim.x - 1);
    }
    __syncthreads();

    // ------------- last block finalizes + resets for next replay -------------
    if (s_last && tid == 0) {
        double base = *((volatile double*)&g_base_sum) / ((double)B * (double)ATM);
        unsigned long long cnt = *((volatile unsigned long long*)&g_cnt);
        double wfa_m = *((volatile double*)&g_wfa_sum) / (double)(cnt > 0 ? cnt : 1);
        bool apply = (base < 0.0004) && (cnt > 0);
        out[0] = apply ? (float)(0.5 * base + 0.5 * wfa_m) : (float)base;
        out[1] = (float)base;
        out[2] = apply ? (float)wfa_m : 0.0f;
        g_base_sum = 0.0;
        g_wfa_sum  = 0.0;
        g_cnt      = 0ull;
        g_done     = 0u;
        __threadfence();
    }
}

extern "C" void kernel_launch(void* const* d_in, const int* in_sizes, int n_in,
                              void* d_out, int out_size) {
    const float* stokes = (const float*)d_in[0];   // (B, 4, 112)
    const float* pred   = (const float*)d_in[1];   // (B, 84)
    const float* targ   = (const float*)d_in[2];   // (B, 84)
    const float* wl     = (const float*)d_in[3];   // (112,)
    const int B = in_sizes[0] / (4 * NWL);
    wfa_fused_kernel<<<BLOCKS, THREADS>>>(stokes, pred, targ, wl, (float*)d_out, B);
}